// round 1
// baseline (speedup 1.0000x reference)
#include <cuda_runtime.h>
#include <cuda_bf16.h>
#include <cstdint>

// Row-wise kernel:
//   center diff of z_1/z_2 (cols 0..3), atan2 -> degrees -> trunc ->
//   clock-shift mod 360 -> zone id in {0..3} -> select dir[row][zone].
// z_3 is unused by the reference (c_3 deleted) -> never read it.
//
// DRAM-bound by design: z_1/z_2 rows are 44B apart with 16B useful -> every
// 32B sector is touched regardless, so scalar LDGs are already optimal.
// dir is loaded as one aligned float4 per row (fully coalesced).

__global__ __launch_bounds__(256)
void yolo_zone_kernel(const float* __restrict__ z1,
                      const float* __restrict__ z2,
                      const float4* __restrict__ dir,
                      float* __restrict__ out,
                      int n)
{
    int i = blockIdx.x * blockDim.x + threadIdx.x;
    if (i >= n) return;

    long base = (long)i * 11;

    // Issue all global loads up front for MLP.
    float a0 = __ldg(z1 + base + 0);
    float a1 = __ldg(z1 + base + 1);
    float a2 = __ldg(z1 + base + 2);
    float a3 = __ldg(z1 + base + 3);
    float b0 = __ldg(z2 + base + 0);
    float b1 = __ldg(z2 + base + 1);
    float b2 = __ldg(z2 + base + 2);
    float b3 = __ldg(z2 + base + 3);
    float4 d = __ldg(dir + i);

    // Centers: (z[0]+z[2])/2, (z[1]+z[3])/2. Division by 2 is exact, so
    // c2-c1 == ((b0+b2)-(a0+a2)) * 0.5f bit-for-bit; keep the faithful form.
    float c1x = (a0 + a2) * 0.5f;
    float c1y = (a1 + a3) * 0.5f;
    float c2x = (b0 + b2) * 0.5f;
    float c2y = (b1 + b3) * 0.5f;

    float dx = c2x - c1x;
    float dy = -(c2y - c1y);

    // degrees(atan2) in fp32, matching jnp.degrees' 180/pi constant.
    float phi = atan2f(dy, dx) * 57.29577951308232f;

    // torch .long() / astype(int32): truncation toward zero.
    int phi_long = (int)phi;

    // python-style mod 360. 90 - phi_long in [-90, 270] -> one conditional add.
    int m = 90 - phi_long;
    if (m < 0) m += 360;
    if (m >= 360) m -= 360;   // defensive (phi_long could be -270.. after fp quirks)

    // zone = floor((m + 45) / 90) mod 4
    int zone = ((m + 45) / 90) & 3;

    float r = (zone == 0) ? d.x : (zone == 1) ? d.y : (zone == 2) ? d.z : d.w;
    out[i] = r;
}

extern "C" void kernel_launch(void* const* d_in, const int* in_sizes, int n_in,
                              void* d_out, int out_size)
{
    const float*  z1  = (const float*)d_in[0];
    const float*  z2  = (const float*)d_in[1];
    // d_in[2] (z_3) intentionally unused — reference discards c_3.
    const float4* dir = (const float4*)d_in[3];
    float*        out = (float*)d_out;

    int n = out_size;               // B rows
    int block = 256;
    int grid = (n + block - 1) / block;
    yolo_zone_kernel<<<grid, block>>>(z1, z2, dir, out, n);
}

// round 2
// speedup vs baseline: 1.1864x; 1.1864x over previous
#include <cuda_runtime.h>
#include <cuda_bf16.h>
#include <cstdint>

// R2: coalesced shared-memory staging.
// z_1/z_2 rows are 44 B apart (D=11 floats) and we need cols 0..3. Instead of
// 8 scalar LDGs per thread (fragmented 44B-stride gather), each block streams
// its full 256-row chunk of z_1 and z_2 as aligned float4s into shared memory,
// then each thread reads its 4 floats from shared (stride-11 words: 11 is
// coprime with 32 -> bank-conflict-free).
//
// Alignment facts (exact for this problem):
//   chunk base  = bid * 256 * 44 B  -> 16B aligned
//   chunk size  = 256 * 44 = 11264 B = 704 float4
//   total       = 2e6 * 44 B, divisible by 16 -> tail block is whole float4s too
//
// z_3 remains unread (reference discards c_3).

constexpr int TPB  = 256;          // threads per block
constexpr int ROWS = 256;          // rows per block (== TPB)
constexpr int WORDS_PER_BLOCK = ROWS * 11;        // 2816 floats
constexpr int F4_PER_BLOCK    = WORDS_PER_BLOCK / 4;  // 704

__global__ __launch_bounds__(TPB)
void yolo_zone_kernel(const float4* __restrict__ z1v,
                      const float4* __restrict__ z2v,
                      const float4* __restrict__ dir,
                      float* __restrict__ out,
                      int n, long nf4)
{
    __shared__ float s1[WORDS_PER_BLOCK];
    __shared__ float s2[WORDS_PER_BLOCK];

    const int t = threadIdx.x;
    const long base4 = (long)blockIdx.x * F4_PER_BLOCK;

    // Stage: 704 float4 per array, 256 threads -> iterations 0..2 (last partial).
    #pragma unroll
    for (int k = 0; k < 3; k++) {
        int  sidx = t + k * TPB;
        long g    = base4 + sidx;
        if (sidx < F4_PER_BLOCK && g < nf4) {
            reinterpret_cast<float4*>(s1)[sidx] = __ldcs(z1v + g);
            reinterpret_cast<float4*>(s2)[sidx] = __ldcs(z2v + g);
        }
    }

    // Overlap the dir load with the staging latency.
    const int row = blockIdx.x * ROWS + t;
    float4 d = make_float4(0.f, 0.f, 0.f, 0.f);
    if (row < n) d = __ldg(dir + row);

    __syncthreads();
    if (row >= n) return;

    const int w = t * 11;
    float a0 = s1[w + 0], a1 = s1[w + 1], a2 = s1[w + 2], a3 = s1[w + 3];
    float b0 = s2[w + 0], b1 = s2[w + 1], b2 = s2[w + 2], b3 = s2[w + 3];

    // Centers and direction vector (division by 2 exact in fp32).
    float dx = (b0 + b2) * 0.5f - (a0 + a2) * 0.5f;
    float dy = -((b1 + b3) * 0.5f - (a1 + a3) * 0.5f);

    // degrees(atan2), truncate toward zero (matches .astype(int32)).
    float phi = atan2f(dy, dx) * 57.29577951308232f;
    int phi_long = (int)phi;

    // python-style mod 360 of (90 - phi_long); range [-90, 270] -> one fixup.
    int m = 90 - phi_long;
    if (m < 0) m += 360;
    if (m >= 360) m -= 360;

    // zone = floor((m + 45) / 90) mod 4
    int zone = ((m + 45) / 90) & 3;

    float r = (zone == 0) ? d.x : (zone == 1) ? d.y : (zone == 2) ? d.z : d.w;
    out[row] = r;
}

extern "C" void kernel_launch(void* const* d_in, const int* in_sizes, int n_in,
                              void* d_out, int out_size)
{
    const float4* z1v = (const float4*)d_in[0];
    const float4* z2v = (const float4*)d_in[1];
    // d_in[2] (z_3) intentionally unused — reference discards c_3.
    const float4* dir = (const float4*)d_in[3];
    float*        out = (float*)d_out;

    int  n   = out_size;                       // B rows
    long nf4 = ((long)n * 11) / 4;             // exact: 2e6*11 divisible by 4

    int grid = (n + ROWS - 1) / ROWS;
    yolo_zone_kernel<<<grid, TPB>>>(z1v, z2v, dir, out, n, nf4);
}